// round 6
// baseline (speedup 1.0000x reference)
#include <cuda_runtime.h>
#include <math.h>

#define BATCH 16
#define HH 512
#define WW 512
#define WIN 15
#define RAD 7
#define OTC 114                 // output cols per tile
#define OTR 32                  // output rows per tile
#define GRX 5                   // ceil(512/114)
#define GRY 16                  // 512/32
#define NT 256
#define NBLOCKS (GRX * GRY * BATCH)   // 1280
#define VP 129                  // vS pitch in float2

#define SMEM_BYTES (OTR * VP * 8)     // 32*129*8 = 33024

__device__ double g_part[NBLOCKS][8];
__device__ unsigned int g_count = 0;

extern __shared__ float2 smem2[];

__global__ void __launch_bounds__(NT, 4)
ncc_main(const float* __restrict__ I, const float* __restrict__ J,
         float* __restrict__ out) {
    float2* vS = smem2;   // vertical (I_sum, J_sum): 32 rows x 128 cols, pitch 129

    const int tid = threadIdx.x;
    const int bx = blockIdx.x, by = blockIdx.y, bz = blockIdx.z;
    const float* __restrict__ Ib = I + (size_t)bz * HH * WW;
    const float* __restrict__ Jb = J + (size_t)bz * HH * WW;

    // ================= Phase A: vertical 15-tap sliding, no ring =============
    // 2 groups x 128 columns; each group produces 16 vS rows from 30 input rows.
    // "Old" window values are re-loaded from global (L1 hit: 15-row reuse window).
    const int tx      = tid & 127;
    const int g       = tid >> 7;
    const int outbase = by * OTR + g * 16;     // first owned output/input row
    const int rowbase = outbase - RAD;         // first streamed input row
    const int gx      = bx * OTC - RAD + tx;
    const bool colok  = (gx >= 0) && (gx < WW);
    const bool ownx   = colok && (tx >= RAD) && (tx < RAD + OTC);
    float wx = 0.f;
    if (ownx) wx = (float)(min(gx + RAD, WW - 1) - max(gx - RAD, 0) + 1);

    float vI = 0.f, vJ = 0.f;
    float pII = 0.f, pJJ = 0.f, pIJ = 0.f;

    // init: rows 0..14 of the stream
    #pragma unroll
    for (int r = 0; r < WIN; r++) {
        const int gy = rowbase + r;
        const bool ok = colok && (gy >= 0) && (gy < HH);
        float vi = 0.f, vj = 0.f;
        if (ok) {
            const int gi = gy * WW + gx;
            vi = __ldg(Ib + gi);
            vj = __ldg(Jb + gi);
        }
        vI += vi; vJ += vj;
        if (r >= RAD && ownx) {                 // owned rows 7..14
            const float wy = (float)(min(gy + RAD, HH - 1) - max(gy - RAD, 0) + 1);
            const float w = wy * wx;
            pII += w * vi * vi;
            pJJ += w * vj * vj;
            pIJ += w * vi * vj;
        }
    }
    vS[(g * 16) * VP + tx] = make_float2(vI, vJ);

    // slides: produce vS rows 1..15 of this group
    #pragma unroll
    for (int i = 0; i < 15; i++) {
        const int gyn = rowbase + WIN + i;      // new row
        const int gyo = rowbase + i;            // old row (re-load, L1 hit)
        const bool okn = colok && (gyn >= 0) && (gyn < HH);
        const bool oko = colok && (gyo >= 0) && (gyo < HH);
        float ni = 0.f, nj = 0.f, oi = 0.f, oj = 0.f;
        if (okn) {
            const int gi = gyn * WW + gx;
            ni = __ldg(Ib + gi);
            nj = __ldg(Jb + gi);
        }
        if (oko) {
            const int gi = gyo * WW + gx;
            oi = __ldg(Ib + gi);
            oj = __ldg(Jb + gi);
        }
        if (i < 8 && ownx) {                    // owned rows 15..22 of stream
            const float wy = (float)(min(gyn + RAD, HH - 1) - max(gyn - RAD, 0) + 1);
            const float w = wy * wx;
            pII += w * ni * ni;
            pJJ += w * nj * nj;
            pIJ += w * ni * nj;
        }
        vI += ni - oi;
        vJ += nj - oj;
        vS[(g * 16 + 1 + i) * VP + tx] = make_float2(vI, vJ);
    }
    __syncthreads();

    // ============= Phase B: horizontal 15-tap slide + quadratics =============
    // row = tid&31 (lane stride 1032B = 2 banks -> conflict-free LDS.64),
    // q = tid>>5 -> col group [q*15, q*15+15).
    const int row = tid & 31;
    const int q   = tid >> 5;
    const int oc0 = q * 15;
    const int ncols = min(OTC, WW - bx * OTC);   // 114 or 56 (bx=4)
    const float2* vrow = vS + row * VP;

    float aSI = 0.f, aSJ = 0.f;
    #pragma unroll
    for (int k = 0; k < WIN; k++) {
        float2 v = vrow[oc0 + k];
        aSI += v.x; aSJ += v.y;
    }
    float sII = 0.f, sJJ = 0.f, sIJ = 0.f;
    #pragma unroll
    for (int i = 0; i < 15; i++) {
        const int oc = oc0 + i;
        if (oc < ncols) {
            sII += aSI * aSI;
            sJJ += aSJ * aSJ;
            sIJ += aSI * aSJ;
        }
        if (i < 14 && oc < OTC - 1) {
            float2 vn = vrow[oc + WIN];
            float2 vo = vrow[oc];
            aSI += vn.x - vo.x;
            aSJ += vn.y - vo.y;
        }
    }

    // ===================== Per-CTA reduction (double) ========================
    double a0 = (double)pII, a1 = (double)pJJ, a2 = (double)pIJ;
    double a3 = (double)sII, a4 = (double)sJJ, a5 = (double)sIJ;
    #pragma unroll
    for (int off = 16; off > 0; off >>= 1) {
        a0 += __shfl_xor_sync(0xFFFFFFFFu, a0, off);
        a1 += __shfl_xor_sync(0xFFFFFFFFu, a1, off);
        a2 += __shfl_xor_sync(0xFFFFFFFFu, a2, off);
        a3 += __shfl_xor_sync(0xFFFFFFFFu, a3, off);
        a4 += __shfl_xor_sync(0xFFFFFFFFu, a4, off);
        a5 += __shfl_xor_sync(0xFFFFFFFFu, a5, off);
    }
    __syncthreads();                       // all phase-B smem reads done
    double* red = (double*)smem2;          // 8 warps x 6 doubles
    const int lane = tid & 31;
    const int warp = tid >> 5;
    if (lane == 0) {
        red[warp * 6 + 0] = a0; red[warp * 6 + 1] = a1; red[warp * 6 + 2] = a2;
        red[warp * 6 + 3] = a3; red[warp * 6 + 4] = a4; red[warp * 6 + 5] = a5;
    }
    __syncthreads();

    const int bid = bx + GRX * (by + GRY * bz);
    __shared__ int s_last;
    if (tid == 0) {
        double t0 = 0, t1 = 0, t2 = 0, t3 = 0, t4 = 0, t5 = 0;
        #pragma unroll
        for (int w = 0; w < NT / 32; w++) {
            t0 += red[w * 6 + 0]; t1 += red[w * 6 + 1]; t2 += red[w * 6 + 2];
            t3 += red[w * 6 + 3]; t4 += red[w * 6 + 4]; t5 += red[w * 6 + 5];
        }
        g_part[bid][0] = t0; g_part[bid][1] = t1; g_part[bid][2] = t2;
        g_part[bid][3] = t3; g_part[bid][4] = t4; g_part[bid][5] = t5;
        __threadfence();
        unsigned int prev = atomicAdd(&g_count, 1u);
        s_last = (prev == NBLOCKS - 1);
    }
    __syncthreads();

    // ================= Last CTA: global reduce + finalize ====================
    if (s_last) {
        double c0 = 0, c1 = 0, c2 = 0, c3 = 0, c4 = 0, c5 = 0;
        for (int c = tid; c < NBLOCKS; c += NT) {
            c0 += g_part[c][0]; c1 += g_part[c][1]; c2 += g_part[c][2];
            c3 += g_part[c][3]; c4 += g_part[c][4]; c5 += g_part[c][5];
        }
        #pragma unroll
        for (int off = 16; off > 0; off >>= 1) {
            c0 += __shfl_xor_sync(0xFFFFFFFFu, c0, off);
            c1 += __shfl_xor_sync(0xFFFFFFFFu, c1, off);
            c2 += __shfl_xor_sync(0xFFFFFFFFu, c2, off);
            c3 += __shfl_xor_sync(0xFFFFFFFFu, c3, off);
            c4 += __shfl_xor_sync(0xFFFFFFFFu, c4, off);
            c5 += __shfl_xor_sync(0xFFFFFFFFu, c5, off);
        }
        __syncthreads();
        if (lane == 0) {
            red[warp * 6 + 0] = c0; red[warp * 6 + 1] = c1; red[warp * 6 + 2] = c2;
            red[warp * 6 + 3] = c3; red[warp * 6 + 4] = c4; red[warp * 6 + 5] = c5;
        }
        __syncthreads();
        if (tid == 0) {
            double t0 = 0, t1 = 0, t2 = 0, t3 = 0, t4 = 0, t5 = 0;
            #pragma unroll
            for (int w = 0; w < NT / 32; w++) {
                t0 += red[w * 6 + 0]; t1 += red[w * 6 + 1]; t2 += red[w * 6 + 2];
                t3 += red[w * 6 + 3]; t4 += red[w * 6 + 4]; t5 += red[w * 6 + 5];
            }
            const double inv = 1.0 / 225.0;
            double cross = t2 - t5 * inv;
            double iv    = t0 - t3 * inv;
            double jv    = t1 - t4 * inv;
            out[0] = (float)(-(cross / sqrt(iv * jv)));
            g_count = 0;    // reset for next graph replay
        }
    }
}

extern "C" void kernel_launch(void* const* d_in, const int* in_sizes, int n_in,
                              void* d_out, int out_size) {
    const float* I = (const float*)d_in[0];
    const float* J = (const float*)d_in[1];
    float* out = (float*)d_out;

    cudaFuncSetAttribute(ncc_main,
                         cudaFuncAttributeMaxDynamicSharedMemorySize, SMEM_BYTES);
    dim3 grid(GRX, GRY, BATCH);   // (5, 16, 16) = 1280 CTAs
    ncc_main<<<grid, NT, SMEM_BYTES>>>(I, J, out);
}

// round 7
// speedup vs baseline: 1.2167x; 1.2167x over previous
#include <cuda_runtime.h>
#include <math.h>

#define BATCH 16
#define HH 512
#define WW 512
#define WIN 15
#define RAD 7
#define OTC 112                 // output cols per tile (4 static strips of 28)
#define OTR 64                  // output rows per tile
#define GRX 5                   // ceil(512/112): tiles 0..3 full, tile 4 = 64 cols
#define GRY 8                   // 512/64
#define NT 256
#define NBLOCKS (GRX * GRY * BATCH)   // 640
#define VP 129                  // vS pitch in float2

#define SMEM_BYTES (OTR * VP * 8)     // 64*129*8 = 66048

__device__ double g_part[NBLOCKS][8];
__device__ unsigned int g_count = 0;

extern __shared__ float2 smem2[];

__global__ void __launch_bounds__(NT, 3)
ncc_main(const float* __restrict__ I, const float* __restrict__ J,
         float* __restrict__ out) {
    float2* vS = smem2;   // vertical (I_sum, J_sum): 64 rows x <=128 cols, pitch 129

    const int tid = threadIdx.x;
    const int bx = blockIdx.x, by = blockIdx.y, bz = blockIdx.z;
    const float* __restrict__ Ib = I + (size_t)bz * HH * WW;
    const float* __restrict__ Jb = J + (size_t)bz * HH * WW;

    // ========== Phase A: vertical 15-tap sliding in registers (ring) =========
    const int tx      = tid & 127;
    const int g       = tid >> 7;
    const int outbase = by * OTR + g * 32;
    const int rowbase = outbase - RAD;
    const int gx      = bx * OTC - RAD + tx;

    float pII = 0.f, pJJ = 0.f, pIJ = 0.f;
    const bool interiorA = (bx >= 1) && (bx <= 3) && (by >= 1) && (by <= 6);

    if (interiorA) {
        // All 46 streamed rows and all 128 lanes are in-bounds; owned pixels
        // have full 15x15 windows -> w = 225 (or 0 for halo columns).
        const float wq = (tx >= RAD && tx < RAD + OTC) ? 225.0f : 0.0f;
        const float* pI = Ib + (size_t)rowbase * WW + gx;
        const float* pJ = Jb + (size_t)rowbase * WW + gx;
        float2 ring[WIN];
        float vI = 0.f, vJ = 0.f;
        #pragma unroll
        for (int r = 0; r < 46; r++) {
            const float vi = __ldg(pI + r * WW);
            const float vj = __ldg(pJ + r * WW);
            if (r >= WIN) { float2 o = ring[r % WIN]; vI -= o.x; vJ -= o.y; }
            ring[r % WIN] = make_float2(vi, vj);
            vI += vi; vJ += vj;
            if (r >= RAD && r < RAD + 32) {      // owned input rows
                pII += wq * vi * vi;
                pJJ += wq * vj * vj;
                pIJ += wq * vi * vj;
            }
            if (r >= WIN - 1)
                vS[(g * 32 + r - (WIN - 1)) * VP + tx] = make_float2(vI, vJ);
        }
    } else {
        // Generic border path (R5 logic)
        const bool colok = (gx >= 0) && (gx < WW);
        const bool ownx  = colok && (tx >= RAD) && (tx < RAD + OTC) && (gx < WW);
        float wx = 0.f;
        if (ownx) wx = (float)(min(gx + RAD, WW - 1) - max(gx - RAD, 0) + 1);

        float2 ring[WIN];
        float vI = 0.f, vJ = 0.f;
        #pragma unroll
        for (int r = 0; r < 46; r++) {
            const int gy = rowbase + r;
            float vi = 0.f, vj = 0.f;
            if (colok && gy >= 0 && gy < HH) {
                const int gi = gy * WW + gx;
                vi = __ldg(Ib + gi);
                vj = __ldg(Jb + gi);
            }
            if (r >= WIN) { float2 o = ring[r % WIN]; vI -= o.x; vJ -= o.y; }
            ring[r % WIN] = make_float2(vi, vj);
            vI += vi; vJ += vj;
            if (r >= RAD && r < RAD + 32 && ownx) {
                const float wy = (float)(min(gy + RAD, HH - 1) - max(gy - RAD, 0) + 1);
                const float w = wy * wx;
                pII += w * vi * vi;
                pJJ += w * vj * vj;
                pIJ += w * vi * vj;
            }
            if (r >= WIN - 1)
                vS[(g * 32 + r - (WIN - 1)) * VP + tx] = make_float2(vI, vJ);
        }
    }
    __syncthreads();

    // ========== Phase B: horizontal 15-tap slide + quadratics ===============
    // row = tid>>2 (0..63), q = tid&3 -> static 28-col strip [q*28, q*28+28).
    const int row = tid >> 2;
    const int q   = tid & 3;
    const int oc0 = q * 28;
    const float2* vrow = vS + row * VP;

    float sII = 0.f, sJJ = 0.f, sIJ = 0.f;
    if (bx < GRX - 1) {
        // Full-width tile: all guards static.
        float2 bring[WIN];
        float aSI = 0.f, aSJ = 0.f;
        #pragma unroll
        for (int k = 0; k < WIN; k++) {
            float2 v = vrow[oc0 + k];
            bring[k] = v;
            aSI += v.x; aSJ += v.y;
        }
        #pragma unroll
        for (int i = 0; i < 28; i++) {
            sII += aSI * aSI;
            sJJ += aSJ * aSJ;
            sIJ += aSI * aSJ;
            if (i < 27) {
                float2 vn = vrow[oc0 + i + WIN];
                float2 vo = bring[i % WIN];
                aSI += vn.x - vo.x;
                aSJ += vn.y - vo.y;
                bring[i % WIN] = vn;
            }
        }
    } else {
        // Last column tile: ncols = 512 - 4*112 = 64.
        const int ncols = WW - (GRX - 1) * OTC;   // 64
        float2 bring[WIN];
        float aSI = 0.f, aSJ = 0.f;
        #pragma unroll
        for (int k = 0; k < WIN; k++) {
            float2 v = vrow[oc0 + k];
            bring[k] = v;
            aSI += v.x; aSJ += v.y;
        }
        #pragma unroll
        for (int i = 0; i < 28; i++) {
            const int oc = oc0 + i;
            if (oc < ncols) {
                sII += aSI * aSI;
                sJJ += aSJ * aSJ;
                sIJ += aSI * aSJ;
            }
            if (i < 27 && oc < ncols - 1) {
                float2 vn = vrow[oc + WIN];
                float2 vo = bring[i % WIN];
                aSI += vn.x - vo.x;
                aSJ += vn.y - vo.y;
                bring[i % WIN] = vn;
            }
        }
    }

    // ===================== Per-CTA reduction (double) ========================
    double a0 = (double)pII, a1 = (double)pJJ, a2 = (double)pIJ;
    double a3 = (double)sII, a4 = (double)sJJ, a5 = (double)sIJ;
    #pragma unroll
    for (int off = 16; off > 0; off >>= 1) {
        a0 += __shfl_xor_sync(0xFFFFFFFFu, a0, off);
        a1 += __shfl_xor_sync(0xFFFFFFFFu, a1, off);
        a2 += __shfl_xor_sync(0xFFFFFFFFu, a2, off);
        a3 += __shfl_xor_sync(0xFFFFFFFFu, a3, off);
        a4 += __shfl_xor_sync(0xFFFFFFFFu, a4, off);
        a5 += __shfl_xor_sync(0xFFFFFFFFu, a5, off);
    }
    __syncthreads();                       // all phase-B smem reads done
    double* red = (double*)smem2;          // 8 warps x 6 doubles
    const int lane = tid & 31;
    const int warp = tid >> 5;
    if (lane == 0) {
        red[warp * 6 + 0] = a0; red[warp * 6 + 1] = a1; red[warp * 6 + 2] = a2;
        red[warp * 6 + 3] = a3; red[warp * 6 + 4] = a4; red[warp * 6 + 5] = a5;
    }
    __syncthreads();

    const int bid = bx + GRX * (by + GRY * bz);
    __shared__ int s_last;
    if (tid == 0) {
        double t0 = 0, t1 = 0, t2 = 0, t3 = 0, t4 = 0, t5 = 0;
        #pragma unroll
        for (int w = 0; w < NT / 32; w++) {
            t0 += red[w * 6 + 0]; t1 += red[w * 6 + 1]; t2 += red[w * 6 + 2];
            t3 += red[w * 6 + 3]; t4 += red[w * 6 + 4]; t5 += red[w * 6 + 5];
        }
        g_part[bid][0] = t0; g_part[bid][1] = t1; g_part[bid][2] = t2;
        g_part[bid][3] = t3; g_part[bid][4] = t4; g_part[bid][5] = t5;
        __threadfence();
        unsigned int prev = atomicAdd(&g_count, 1u);
        s_last = (prev == NBLOCKS - 1);
    }
    __syncthreads();

    // ================= Last CTA: global reduce + finalize ====================
    if (s_last) {
        double c0 = 0, c1 = 0, c2 = 0, c3 = 0, c4 = 0, c5 = 0;
        for (int c = tid; c < NBLOCKS; c += NT) {
            c0 += g_part[c][0]; c1 += g_part[c][1]; c2 += g_part[c][2];
            c3 += g_part[c][3]; c4 += g_part[c][4]; c5 += g_part[c][5];
        }
        #pragma unroll
        for (int off = 16; off > 0; off >>= 1) {
            c0 += __shfl_xor_sync(0xFFFFFFFFu, c0, off);
            c1 += __shfl_xor_sync(0xFFFFFFFFu, c1, off);
            c2 += __shfl_xor_sync(0xFFFFFFFFu, c2, off);
            c3 += __shfl_xor_sync(0xFFFFFFFFu, c3, off);
            c4 += __shfl_xor_sync(0xFFFFFFFFu, c4, off);
            c5 += __shfl_xor_sync(0xFFFFFFFFu, c5, off);
        }
        __syncthreads();
        if (lane == 0) {
            red[warp * 6 + 0] = c0; red[warp * 6 + 1] = c1; red[warp * 6 + 2] = c2;
            red[warp * 6 + 3] = c3; red[warp * 6 + 4] = c4; red[warp * 6 + 5] = c5;
        }
        __syncthreads();
        if (tid == 0) {
            double t0 = 0, t1 = 0, t2 = 0, t3 = 0, t4 = 0, t5 = 0;
            #pragma unroll
            for (int w = 0; w < NT / 32; w++) {
                t0 += red[w * 6 + 0]; t1 += red[w * 6 + 1]; t2 += red[w * 6 + 2];
                t3 += red[w * 6 + 3]; t4 += red[w * 6 + 4]; t5 += red[w * 6 + 5];
            }
            const double inv = 1.0 / 225.0;
            double cross = t2 - t5 * inv;
            double iv    = t0 - t3 * inv;
            double jv    = t1 - t4 * inv;
            out[0] = (float)(-(cross / sqrt(iv * jv)));
            g_count = 0;    // reset for next graph replay
        }
    }
}

extern "C" void kernel_launch(void* const* d_in, const int* in_sizes, int n_in,
                              void* d_out, int out_size) {
    const float* I = (const float*)d_in[0];
    const float* J = (const float*)d_in[1];
    float* out = (float*)d_out;

    cudaFuncSetAttribute(ncc_main,
                         cudaFuncAttributeMaxDynamicSharedMemorySize, SMEM_BYTES);
    dim3 grid(GRX, GRY, BATCH);   // (5, 8, 16) = 640 CTAs
    ncc_main<<<grid, NT, SMEM_BYTES>>>(I, J, out);
}